// round 6
// baseline (speedup 1.0000x reference)
#include <cuda_runtime.h>
#include <cuda_bf16.h>
#include <stdint.h>
#include <math.h>

#define EMB   512
#define VOCAB 32000
#define HID   1024
#define STY   512
#define NB    32
#define SEQ   64
#define TSTEPS 63
#define MROWS (TSTEPS*NB)   /* 2016 */
#define MPAD  2048

// ---------------- device scratch (zero-initialized .bss) ----------------
__device__ float g_Gx[(size_t)MPAD*4*HID];
__device__ float g_hbuf[2*NB*HID];
__device__ float g_c [NB*HID];
__device__ float g_bias3[4*HID];
__device__ __nv_bfloat16 g_Xh[MPAD*EMB],     g_Xl[MPAD*EMB];
__device__ __nv_bfloat16 g_Uh[MPAD*4*STY],   g_Ul[MPAD*4*STY];
__device__ __nv_bfloat16 g_Sh[MPAD*STY],     g_Sl[MPAD*STY];
__device__ __nv_bfloat16 g_Hh[MPAD*HID],     g_Hl[MPAD*HID];   // rows>=2016 stay 0
__device__ __nv_bfloat16 g_Bh[(size_t)VOCAB*1024], g_Bl[(size_t)VOCAB*1024];

// ---------------- helpers ----------------
static __device__ __forceinline__ uint32_t smem_u32(const void* p) {
    uint32_t a;
    asm("{ .reg .u64 t; cvta.to.shared.u64 t, %1; cvt.u32.u64 %0, t; }" : "=r"(a) : "l"(p));
    return a;
}
static __device__ __forceinline__ void cvt2(float f, unsigned& h, unsigned& l) {
    __nv_bfloat16 hb = __float2bfloat16_rn(f);
    float rem = f - __bfloat162float(hb);
    __nv_bfloat16 lb = __float2bfloat16_rn(rem);
    h = (unsigned)__bfloat16_as_ushort(hb);
    l = (unsigned)__bfloat16_as_ushort(lb);
}
static __device__ __forceinline__ void ldm4(uint32_t addr, uint32_t* r) {
    asm volatile("ldmatrix.sync.aligned.m8n8.x4.shared.b16 {%0,%1,%2,%3}, [%4];"
        : "=r"(r[0]), "=r"(r[1]), "=r"(r[2]), "=r"(r[3]) : "r"(addr));
}
static __device__ __forceinline__ void mma16816(float* d, const uint32_t* a,
                                                const uint32_t* b) {
    asm volatile("mma.sync.aligned.m16n8k16.row.col.f32.bf16.bf16.f32 "
        "{%0,%1,%2,%3},{%4,%5,%6,%7},{%8,%9},{%0,%1,%2,%3};"
        : "+f"(d[0]), "+f"(d[1]), "+f"(d[2]), "+f"(d[3])
        : "r"(a[0]), "r"(a[1]), "r"(a[2]), "r"(a[3]), "r"(b[0]), "r"(b[1]));
}
static __device__ __forceinline__ void cpa16(uint32_t s, const void* g) {
    asm volatile("cp.async.cg.shared.global [%0], [%1], 16;" :: "r"(s), "l"(g));
}
static __device__ __forceinline__ void cpcommit() {
    asm volatile("cp.async.commit_group;" ::: "memory");
}
template<int n> static __device__ __forceinline__ void cpwait() {
    asm volatile("cp.async.wait_group %0;" :: "n"(n) : "memory");
}

// ---------------- gather ----------------
__global__ void k_gather(const int* __restrict__ idx, const float* __restrict__ embed,
                         __nv_bfloat16* __restrict__ Xh, __nv_bfloat16* __restrict__ Xl)
{
    int t = blockIdx.x, b = blockIdx.y;
    int tok = idx[b*SEQ + t];
    float4 v = ((const float4*)(embed + (size_t)tok*EMB))[threadIdx.x];
    unsigned h0,l0,h1,l1,h2,l2,h3,l3;
    cvt2(v.x,h0,l0); cvt2(v.y,h1,l1); cvt2(v.z,h2,l2); cvt2(v.w,h3,l3);
    uint2 hv; hv.x = h0|(h1<<16); hv.y = h2|(h3<<16);
    uint2 lv; lv.x = l0|(l1<<16); lv.y = l2|(l3<<16);
    size_t o = (size_t)(t*NB + b)*EMB + threadIdx.x*4;
    *(uint2*)(Xh + o) = hv;
    *(uint2*)(Xl + o) = lv;
}

// ---------------- init ----------------
__global__ void k_init(const float* __restrict__ sv, const float* __restrict__ Vb,
                       const float* __restrict__ Wb, float* __restrict__ h0,
                       float* __restrict__ c, float* __restrict__ b3)
{
    int i = blockIdx.x*blockDim.x + threadIdx.x;
    if (i < NB*HID) { h0[i] = sv[i]; c[i] = sv[i]; }
    if (i < 4*HID)  b3[i] = Vb[i] + Wb[i];
}

// ---------------- convert + transpose: fp32 [K][N] -> bf16 hi/lo [N][K] ----------------
__global__ void k_convT(const float* __restrict__ in, __nv_bfloat16* __restrict__ hiT,
                        __nv_bfloat16* __restrict__ loT, int K, int N)
{
    __shared__ float s[32][33];
    const int k0 = blockIdx.y*32, n0 = blockIdx.x*32;
    const int tid = threadIdx.x;
    {
        int r = tid>>3, c4 = (tid&7)*4;
        float4 v = *(const float4*)(in + (size_t)(k0+r)*N + n0 + c4);
        s[r][c4+0]=v.x; s[r][c4+1]=v.y; s[r][c4+2]=v.z; s[r][c4+3]=v.w;
    }
    __syncthreads();
    {
        int n = tid>>3, kq = (tid&7)*4;
        unsigned hh[4], ll[4];
#pragma unroll
        for (int i = 0; i < 4; ++i) cvt2(s[kq+i][n], hh[i], ll[i]);
        uint2 hv; hv.x = hh[0]|(hh[1]<<16); hv.y = hh[2]|(hh[3]<<16);
        uint2 lv; lv.x = ll[0]|(ll[1]<<16); lv.y = ll[2]|(ll[3]<<16);
        size_t o = ((size_t)(n0+n)*K + k0 + kq);
        *(uint2*)(hiT + o) = hv;
        *(uint2*)(loT + o) = lv;
    }
}

// ============ HMMA GEMM, 3-stage cp.async pipeline ============
// A: bf16 hi/lo [M][K]; B: bf16 hi/lo [N][K]; C fp32 and/or Chi/Clo bf16 outputs.
// Block tile 128x64, 8 warps of 32x32, Kc=32, 3-term bf16 split, fp32 accum.
// smem: 3 stages x (Ah 8K | Al 8K | Bh 4K | Bl 4K) = 72KB dynamic.
#define STG   24576
#define AL_O  8192
#define BH_O  16384
#define BL_O  20480
#define TG_SMEM (3*STG)
static __device__ __forceinline__ uint32_t swz64(int row, int k16) {
    return (uint32_t)(row*64 + ((k16 ^ ((row>>1)&3))<<4));
}

__global__ __launch_bounds__(256)
void k_mgemm(const __nv_bfloat16* __restrict__ Ah, const __nv_bfloat16* __restrict__ Al,
             const __nv_bfloat16* __restrict__ Bh, const __nv_bfloat16* __restrict__ Bl,
             const float* __restrict__ bias, float* __restrict__ C,
             __nv_bfloat16* __restrict__ Chi, __nv_bfloat16* __restrict__ Clo,
             int N, int K, int Mstore)
{
    extern __shared__ __align__(16) unsigned char sm[];
    const uint32_t sbase = smem_u32(sm);

    const int tid = threadIdx.x, lane = tid & 31, wid = tid >> 5;
    const int brow = blockIdx.x*128, bcol = blockIdx.y*64;

    // cp.async per-thread assignments
    const int arow = tid >> 1, ak = (tid & 1)*2;             // A: 2 threads/row
    const uint32_t csA0 = sbase + swz64(arow, ak);
    const uint32_t csA1 = sbase + swz64(arow, ak+1);
    const __nv_bfloat16* gAh_t = Ah + (size_t)(brow + arow)*K + ak*8;
    const __nv_bfloat16* gAl_t = Al + (size_t)(brow + arow)*K + ak*8;
    const int bn = tid >> 2, bk = tid & 3;                   // B: 4 threads/row
    const uint32_t csB = sbase + BH_O + swz64(bn, bk);
    const __nv_bfloat16* gBh_t = Bh + (size_t)(bcol + bn)*K + bk*8;
    const __nv_bfloat16* gBl_t = Bl + (size_t)(bcol + bn)*K + bk*8;

    // warp tile 32x32 at (m0w, n0w)
    const int m0w = (wid & 3)*32, n0w = (wid >> 2)*32;
    const int arL = lane & 15;
    const int srA = (arL >> 1) & 3;
    const int brL = (lane & 7) + ((lane >> 4) << 3);
    const int srB = ((lane & 7) >> 1) & 3;
    const uint32_t aRowOff = (uint32_t)(m0w + arL)*64;
    const uint32_t bRowOff = (uint32_t)(n0w + brL)*64 + BH_O;

    float acc[2][4][4];
#pragma unroll
    for (int i = 0; i < 2; ++i)
#pragma unroll
        for (int j = 0; j < 4; ++j)
#pragma unroll
            for (int q = 0; q < 4; ++q) acc[i][j][q] = 0.f;

    const int nch = K >> 5;

    // prologue: issue chunks 0 and 1 into stages 0 and 1
    {
        cpa16(csA0, gAh_t); cpa16(csA1, gAh_t + 8);
        cpa16(csA0 + AL_O, gAl_t); cpa16(csA1 + AL_O, gAl_t + 8);
        cpa16(csB, gBh_t); cpa16(csB + (BL_O - BH_O), gBl_t);
        cpcommit();
        if (nch > 1) {
            cpa16(csA0 + STG, gAh_t + 32); cpa16(csA1 + STG, gAh_t + 40);
            cpa16(csA0 + AL_O + STG, gAl_t + 32); cpa16(csA1 + AL_O + STG, gAl_t + 40);
            cpa16(csB + STG, gBh_t + 32); cpa16(csB + (BL_O - BH_O) + STG, gBl_t + 32);
            cpcommit();
        }
    }

    int scmp = 0;   // stage holding chunk c
    int siss = 2;   // stage to fill with chunk c+2
    for (int c = 0; c < nch; ++c) {
        if (c + 1 < nch) cpwait<1>(); else cpwait<0>();
        __syncthreads();   // chunk c visible to all; stage siss vacated by all warps

        if (c + 2 < nch) {
            const uint32_t so = (uint32_t)siss*STG;
            const int kc = (c+2)*32;
            cpa16(csA0 + so, gAh_t + kc); cpa16(csA1 + so, gAh_t + kc + 8);
            cpa16(csA0 + AL_O + so, gAl_t + kc); cpa16(csA1 + AL_O + so, gAl_t + kc + 8);
            cpa16(csB + so, gBh_t + kc); cpa16(csB + (BL_O - BH_O) + so, gBl_t + kc);
            cpcommit();
        }

        const uint32_t sb_s = sbase + (uint32_t)scmp*STG;
#pragma unroll
        for (int kk = 0; kk < 32; kk += 16) {
            uint32_t ah[2][4], al[2][4], bh[2][4], bl[2][4];
            const int k16a = (kk >> 3) + (lane >> 4);
            const uint32_t abase = sb_s + aRowOff + ((uint32_t)(k16a ^ srA) << 4);
            ldm4(abase, ah[0]);           ldm4(abase + 16*64, ah[1]);
            ldm4(abase + AL_O, al[0]);    ldm4(abase + AL_O + 16*64, al[1]);
            const int k16b = (kk >> 3) + ((lane >> 3) & 1);
            const uint32_t bbase = sb_s + bRowOff + ((uint32_t)(k16b ^ srB) << 4);
            ldm4(bbase, bh[0]);           ldm4(bbase + 16*64, bh[1]);
            ldm4(bbase + 4096, bl[0]);    ldm4(bbase + 4096 + 16*64, bl[1]);
#pragma unroll
            for (int mt = 0; mt < 2; ++mt)
#pragma unroll
                for (int nt = 0; nt < 4; ++nt) {
                    const int ng = nt >> 1, sel = (nt & 1)*2;
                    mma16816(acc[mt][nt], ah[mt], &bh[ng][sel]);
                    mma16816(acc[mt][nt], ah[mt], &bl[ng][sel]);
                    mma16816(acc[mt][nt], al[mt], &bh[ng][sel]);
                }
        }
        scmp = (scmp == 2) ? 0 : scmp + 1;
        siss = (siss == 2) ? 0 : siss + 1;
    }

    // epilogue
    const int g = lane >> 2, tg = lane & 3;
#pragma unroll
    for (int mt = 0; mt < 2; ++mt)
#pragma unroll
        for (int nt = 0; nt < 4; ++nt) {
            const int col = bcol + n0w + nt*8 + tg*2;
            const float b0 = bias[col], b1 = bias[col+1];
#pragma unroll
            for (int half = 0; half < 2; ++half) {
                const int row = brow + m0w + mt*16 + g + half*8;
                if (row < Mstore) {
                    float o0 = acc[mt][nt][half*2+0] + b0;
                    float o1 = acc[mt][nt][half*2+1] + b1;
                    const size_t o = (size_t)row*N + col;
                    if (C) { float2 v; v.x = o0; v.y = o1; *(float2*)(C + o) = v; }
                    if (Chi) {
                        unsigned h0,l0,h1,l1;
                        cvt2(o0,h0,l0); cvt2(o1,h1,l1);
                        *(uint32_t*)(Chi + o) = h0 | (h1<<16);
                        *(uint32_t*)(Clo + o) = l0 | (l1<<16);
                    }
                }
            }
        }
}

// ---------------- fused LSTM step ----------------
__global__ __launch_bounds__(256)
void k_step(const float* __restrict__ Gx, const float* __restrict__ W,
            const float* __restrict__ h_in, float* __restrict__ h_out,
            float* __restrict__ c,
            __nv_bfloat16* __restrict__ Hh, __nv_bfloat16* __restrict__ Hl, int t)
{
    __shared__ float Hs[32][36];
    __shared__ float Ws[32][32];
    __shared__ float Gs[32][32];

    const int tid = threadIdx.x;
    const int n0 = blockIdx.x * 8;
    const int col_local = tid & 31;
    const int gate = col_local >> 3;
    const int n_local = col_local & 7;
    const int gcol = gate*HID + n0 + n_local;
    const int bgrp = tid >> 5;

    float acc0 = Gx[(size_t)(t*NB + bgrp*4 + 0)*(4*HID) + gcol];
    float acc1 = Gx[(size_t)(t*NB + bgrp*4 + 1)*(4*HID) + gcol];
    float acc2 = Gx[(size_t)(t*NB + bgrp*4 + 2)*(4*HID) + gcol];
    float acc3 = Gx[(size_t)(t*NB + bgrp*4 + 3)*(4*HID) + gcol];

    const int hr = tid >> 3;
    const int hc = (tid & 7) * 4;
    const int k4 = (tid >> 5) * 4;

    for (int kb = 0; kb < HID; kb += 32) {
        float4 hv = *(const float4*)(h_in + (size_t)hr*HID + kb + hc);
        Hs[hr][hc+0] = hv.x; Hs[hr][hc+1] = hv.y;
        Hs[hr][hc+2] = hv.z; Hs[hr][hc+3] = hv.w;
#pragma unroll
        for (int kk = 0; kk < 4; kk++)
            Ws[k4+kk][col_local] = W[(size_t)(kb + k4 + kk)*(4*HID) + gcol];
        __syncthreads();
#pragma unroll
        for (int k = 0; k < 32; k++) {
            float w = Ws[k][col_local];
            acc0 += Hs[bgrp*4+0][k] * w;
            acc1 += Hs[bgrp*4+1][k] * w;
            acc2 += Hs[bgrp*4+2][k] * w;
            acc3 += Hs[bgrp*4+3][k] * w;
        }
        __syncthreads();
    }

    Gs[bgrp*4+0][col_local] = acc0;
    Gs[bgrp*4+1][col_local] = acc1;
    Gs[bgrp*4+2][col_local] = acc2;
    Gs[bgrp*4+3][col_local] = acc3;
    __syncthreads();

    const int b = tid >> 3;
    const int nn = tid & 7;
    float gi = Gs[b][0*8 + nn];
    float gf = Gs[b][1*8 + nn];
    float go = Gs[b][2*8 + nn];
    float gc = Gs[b][3*8 + nn];
    int n_glob = n0 + nn;
    float cv = c[(size_t)b*HID + n_glob];
    float si = 1.f / (1.f + expf(-gi));
    float sf = 1.f / (1.f + expf(-gf));
    float so = 1.f / (1.f + expf(-go));
    float c_new = sf * cv + si * tanhf(gc);
    float h_new = so * c_new;
    c[(size_t)b*HID + n_glob] = c_new;
    h_out[(size_t)b*HID + n_glob] = h_new;
    unsigned hh, ll;
    cvt2(h_new, hh, ll);
    size_t ho = (size_t)(b*TSTEPS + t)*HID + n_glob;
    ((unsigned short*)Hh)[ho] = (unsigned short)hh;
    ((unsigned short*)Hl)[ho] = (unsigned short)ll;
}

// ---------------- launch ----------------
extern "C" void kernel_launch(void* const* d_in, const int* in_sizes, int n_in,
                              void* d_out, int out_size)
{
    const int*   rnn   = (const int*)  d_in[0];
    const float* sv    = (const float*)d_in[1];
    const float* embed = (const float*)d_in[2];
    const float* U_w   = (const float*)d_in[3];
    const float* U_b   = (const float*)d_in[4];
    const float* S1_w  = (const float*)d_in[5];
    const float* S1_b  = (const float*)d_in[6];
    const float* V_w   = (const float*)d_in[7];
    const float* W_w   = (const float*)d_in[9];
    const float* P_w   = (const float*)d_in[11];
    const float* P_b   = (const float*)d_in[12];
    float* out = (float*)d_out;

    float *Gx,*hb,*c,*b3;
    __nv_bfloat16 *Xh,*Xl,*Uh,*Ul,*Sh,*Sl,*Hh,*Hl,*Bh,*Bl;
    cudaGetSymbolAddress((void**)&Gx, g_Gx);
    cudaGetSymbolAddress((void**)&hb, g_hbuf);
    cudaGetSymbolAddress((void**)&c,  g_c);
    cudaGetSymbolAddress((void**)&b3, g_bias3);
    cudaGetSymbolAddress((void**)&Xh, g_Xh); cudaGetSymbolAddress((void**)&Xl, g_Xl);
    cudaGetSymbolAddress((void**)&Uh, g_Uh); cudaGetSymbolAddress((void**)&Ul, g_Ul);
    cudaGetSymbolAddress((void**)&Sh, g_Sh); cudaGetSymbolAddress((void**)&Sl, g_Sl);
    cudaGetSymbolAddress((void**)&Hh, g_Hh); cudaGetSymbolAddress((void**)&Hl, g_Hl);
    cudaGetSymbolAddress((void**)&Bh, g_Bh); cudaGetSymbolAddress((void**)&Bl, g_Bl);
    float* h0 = hb;
    float* h1 = hb + NB*HID;

    cudaFuncSetAttribute(k_mgemm, cudaFuncAttributeMaxDynamicSharedMemorySize, TG_SMEM);

    k_gather<<<dim3(TSTEPS, NB), 128>>>(rnn, embed, Xh, Xl);
    k_init<<<(NB*HID + 255)/256, 256>>>(sv, (const float*)d_in[8],
                                        (const float*)d_in[10], h0, c, b3);

    // GEMM1: U = X @ U_w + U_b -> bf16 hi/lo only
    k_convT<<<dim3((4*STY)/32, EMB/32), 256>>>(U_w, Bh, Bl, EMB, 4*STY);
    k_mgemm<<<dim3(MPAD/128, (4*STY)/64), 256, TG_SMEM>>>(Xh, Xl, Bh, Bl, U_b,
                                                 nullptr, Uh, Ul, 4*STY, EMB, MPAD);
    // GEMM2: S = U @ S1_w + S1_b -> bf16 hi/lo only
    k_convT<<<dim3(STY/32, (4*STY)/32), 256>>>(S1_w, Bh, Bl, 4*STY, STY);
    k_mgemm<<<dim3(MPAD/128, STY/64), 256, TG_SMEM>>>(Uh, Ul, Bh, Bl, S1_b,
                                             nullptr, Sh, Sl, STY, 4*STY, MPAD);
    // GEMM3: Gx = S @ V_w + (V_b+W_b) -> fp32 only
    k_convT<<<dim3((4*HID)/32, STY/32), 256>>>(V_w, Bh, Bl, STY, 4*HID);
    k_mgemm<<<dim3(MPAD/128, (4*HID)/64), 256, TG_SMEM>>>(Sh, Sl, Bh, Bl, b3,
                                                 Gx, nullptr, nullptr, 4*HID, STY, MPAD);

    // recurrence: 63 sequential fused steps, h logged as bf16 hi/lo
    for (int t = 0; t < TSTEPS; t++) {
        float* hin  = (t & 1) ? h1 : h0;
        float* hout = (t & 1) ? h0 : h1;
        k_step<<<HID/8, 256>>>(Gx, W_w, hin, hout, c, Hh, Hl, t);
    }

    // GEMM4: out = H @ P_w + P_b -> fp32 d_out
    k_convT<<<dim3(VOCAB/32, HID/32), 256>>>(P_w, Bh, Bl, HID, VOCAB);
    k_mgemm<<<dim3(MPAD/128, VOCAB/64), 256, TG_SMEM>>>(Hh, Hl, Bh, Bl, P_b,
                                               out, nullptr, nullptr, VOCAB, HID, MROWS);
}

// round 7
// speedup vs baseline: 1.0397x; 1.0397x over previous
#include <cuda_runtime.h>
#include <cuda_bf16.h>
#include <stdint.h>
#include <math.h>

#define EMB   512
#define VOCAB 32000
#define HID   1024
#define STY   512
#define NB    32
#define SEQ   64
#define TSTEPS 63
#define MROWS (TSTEPS*NB)   /* 2016 */
#define MPAD  2048

// ---------------- device scratch (zero-initialized .bss) ----------------
__device__ float g_Gx[(size_t)MPAD*4*HID];
__device__ float g_hbuf[2*NB*HID];
__device__ float g_c [NB*HID];
__device__ float g_bias3[4*HID];
__device__ __nv_bfloat16 g_Xh[MPAD*EMB],     g_Xl[MPAD*EMB];
__device__ __nv_bfloat16 g_Uh[MPAD*4*STY],   g_Ul[MPAD*4*STY];
__device__ __nv_bfloat16 g_Sh[MPAD*STY],     g_Sl[MPAD*STY];
__device__ __nv_bfloat16 g_Hh[MPAD*HID],     g_Hl[MPAD*HID];   // rows>=2016 stay 0
__device__ __nv_bfloat16 g_Bh[(size_t)VOCAB*1024], g_Bl[(size_t)VOCAB*1024];

// ---------------- helpers ----------------
static __device__ __forceinline__ uint32_t smem_u32(const void* p) {
    uint32_t a;
    asm("{ .reg .u64 t; cvta.to.shared.u64 t, %1; cvt.u32.u64 %0, t; }" : "=r"(a) : "l"(p));
    return a;
}
static __device__ __forceinline__ void cvt2(float f, unsigned& h, unsigned& l) {
    __nv_bfloat16 hb = __float2bfloat16_rn(f);
    float rem = f - __bfloat162float(hb);
    __nv_bfloat16 lb = __float2bfloat16_rn(rem);
    h = (unsigned)__bfloat16_as_ushort(hb);
    l = (unsigned)__bfloat16_as_ushort(lb);
}
static __device__ __forceinline__ void ldm4(uint32_t addr, uint32_t* r) {
    asm volatile("ldmatrix.sync.aligned.m8n8.x4.shared.b16 {%0,%1,%2,%3}, [%4];"
        : "=r"(r[0]), "=r"(r[1]), "=r"(r[2]), "=r"(r[3]) : "r"(addr));
}
static __device__ __forceinline__ void mma16816(float* d, const uint32_t* a,
                                                const uint32_t* b) {
    asm volatile("mma.sync.aligned.m16n8k16.row.col.f32.bf16.bf16.f32 "
        "{%0,%1,%2,%3},{%4,%5,%6,%7},{%8,%9},{%0,%1,%2,%3};"
        : "+f"(d[0]), "+f"(d[1]), "+f"(d[2]), "+f"(d[3])
        : "r"(a[0]), "r"(a[1]), "r"(a[2]), "r"(a[3]), "r"(b[0]), "r"(b[1]));
}
static __device__ __forceinline__ void cpa16(uint32_t s, const void* g) {
    asm volatile("cp.async.cg.shared.global [%0], [%1], 16;" :: "r"(s), "l"(g));
}
static __device__ __forceinline__ void cpcommit() {
    asm volatile("cp.async.commit_group;" ::: "memory");
}
template<int n> static __device__ __forceinline__ void cpwait() {
    asm volatile("cp.async.wait_group %0;" :: "n"(n) : "memory");
}

// ---------------- gather ----------------
__global__ void k_gather(const int* __restrict__ idx, const float* __restrict__ embed,
                         __nv_bfloat16* __restrict__ Xh, __nv_bfloat16* __restrict__ Xl)
{
    int t = blockIdx.x, b = blockIdx.y;
    int tok = idx[b*SEQ + t];
    float4 v = ((const float4*)(embed + (size_t)tok*EMB))[threadIdx.x];
    unsigned h0,l0,h1,l1,h2,l2,h3,l3;
    cvt2(v.x,h0,l0); cvt2(v.y,h1,l1); cvt2(v.z,h2,l2); cvt2(v.w,h3,l3);
    uint2 hv; hv.x = h0|(h1<<16); hv.y = h2|(h3<<16);
    uint2 lv; lv.x = l0|(l1<<16); lv.y = l2|(l3<<16);
    size_t o = (size_t)(t*NB + b)*EMB + threadIdx.x*4;
    *(uint2*)(Xh + o) = hv;
    *(uint2*)(Xl + o) = lv;
}

// ---------------- init ----------------
__global__ void k_init(const float* __restrict__ sv, const float* __restrict__ Vb,
                       const float* __restrict__ Wb, float* __restrict__ h0,
                       float* __restrict__ c, float* __restrict__ b3)
{
    int i = blockIdx.x*blockDim.x + threadIdx.x;
    if (i < NB*HID) { h0[i] = sv[i]; c[i] = sv[i]; }
    if (i < 4*HID)  b3[i] = Vb[i] + Wb[i];
}

// ---------------- convert + transpose: fp32 [K][N] -> bf16 hi/lo [N][K] ----------------
__global__ void k_convT(const float* __restrict__ in, __nv_bfloat16* __restrict__ hiT,
                        __nv_bfloat16* __restrict__ loT, int K, int N)
{
    __shared__ float s[32][33];
    const int k0 = blockIdx.y*32, n0 = blockIdx.x*32;
    const int tid = threadIdx.x;
    {
        int r = tid>>3, c4 = (tid&7)*4;
        float4 v = *(const float4*)(in + (size_t)(k0+r)*N + n0 + c4);
        s[r][c4+0]=v.x; s[r][c4+1]=v.y; s[r][c4+2]=v.z; s[r][c4+3]=v.w;
    }
    __syncthreads();
    {
        int n = tid>>3, kq = (tid&7)*4;
        unsigned hh[4], ll[4];
#pragma unroll
        for (int i = 0; i < 4; ++i) cvt2(s[kq+i][n], hh[i], ll[i]);
        uint2 hv; hv.x = hh[0]|(hh[1]<<16); hv.y = hh[2]|(hh[3]<<16);
        uint2 lv; lv.x = ll[0]|(ll[1]<<16); lv.y = ll[2]|(ll[3]<<16);
        size_t o = ((size_t)(n0+n)*K + k0 + kq);
        *(uint2*)(hiT + o) = hv;
        *(uint2*)(loT + o) = lv;
    }
}

// ============ HMMA GEMM, 2-stage cp.async, term-outer MMA order ============
// A: bf16 hi/lo [M][K]; B: bf16 hi/lo [N][K]; C fp32 and/or Chi/Clo bf16 outputs.
// Block tile 128x64, 8 warps of 32x32, Kc=32, 3-term bf16 split, fp32 accum.
// smem: 2 stages x (Ah 8K | Al 8K | Bh 4K | Bl 4K) = 48KB static. 3 CTAs/SM.
#define STG   24576
#define AL_O  8192
#define BH_O  16384
#define BL_O  20480
static __device__ __forceinline__ uint32_t swz64(int row, int k16) {
    return (uint32_t)(row*64 + ((k16 ^ ((row>>1)&3))<<4));
}

__global__ __launch_bounds__(256, 3)
void k_mgemm(const __nv_bfloat16* __restrict__ Ah, const __nv_bfloat16* __restrict__ Al,
             const __nv_bfloat16* __restrict__ Bh, const __nv_bfloat16* __restrict__ Bl,
             const float* __restrict__ bias, float* __restrict__ C,
             __nv_bfloat16* __restrict__ Chi, __nv_bfloat16* __restrict__ Clo,
             int N, int K, int Mstore)
{
    __shared__ __align__(16) unsigned char sm[2*STG];
    const uint32_t sbase = smem_u32(sm);

    const int tid = threadIdx.x, lane = tid & 31, wid = tid >> 5;
    const int brow = blockIdx.x*128, bcol = blockIdx.y*64;

    // cp.async per-thread assignments
    const int arow = tid >> 1, ak = (tid & 1)*2;             // A: 2 threads/row
    const uint32_t csA0 = sbase + swz64(arow, ak);
    const uint32_t csA1 = sbase + swz64(arow, ak+1);
    const __nv_bfloat16* gAh_t = Ah + (size_t)(brow + arow)*K + ak*8;
    const __nv_bfloat16* gAl_t = Al + (size_t)(brow + arow)*K + ak*8;
    const int bn = tid >> 2, bk = tid & 3;                   // B: 4 threads/row
    const uint32_t csB = sbase + BH_O + swz64(bn, bk);
    const __nv_bfloat16* gBh_t = Bh + (size_t)(bcol + bn)*K + bk*8;
    const __nv_bfloat16* gBl_t = Bl + (size_t)(bcol + bn)*K + bk*8;

    // warp tile 32x32 at (m0w, n0w)
    const int m0w = (wid & 3)*32, n0w = (wid >> 2)*32;
    const int arL = lane & 15;
    const int srA = (arL >> 1) & 3;
    const int brL = (lane & 7) + ((lane >> 4) << 3);
    const int srB = ((lane & 7) >> 1) & 3;
    const uint32_t aRowOff = (uint32_t)(m0w + arL)*64;
    const uint32_t bRowOff = (uint32_t)(n0w + brL)*64 + BH_O;

    float acc[2][4][4];
#pragma unroll
    for (int i = 0; i < 2; ++i)
#pragma unroll
        for (int j = 0; j < 4; ++j)
#pragma unroll
            for (int q = 0; q < 4; ++q) acc[i][j][q] = 0.f;

    const int nch = K >> 5;

    // prologue: stage 0 <- chunk 0
    {
        cpa16(csA0, gAh_t); cpa16(csA1, gAh_t + 8);
        cpa16(csA0 + AL_O, gAl_t); cpa16(csA1 + AL_O, gAl_t + 8);
        cpa16(csB, gBh_t); cpa16(csB + (BL_O - BH_O), gBl_t);
        cpcommit();
    }

    for (int c = 0; c < nch; ++c) {
        if (c + 1 < nch) {
            const uint32_t so = (uint32_t)((c+1) & 1)*STG;
            const int kc = (c+1)*32;
            cpa16(csA0 + so, gAh_t + kc); cpa16(csA1 + so, gAh_t + kc + 8);
            cpa16(csA0 + AL_O + so, gAl_t + kc); cpa16(csA1 + AL_O + so, gAl_t + kc + 8);
            cpa16(csB + so, gBh_t + kc); cpa16(csB + (BL_O - BH_O) + so, gBl_t + kc);
            cpcommit();
            cpwait<1>();
        } else {
            cpwait<0>();
        }
        __syncthreads();

        const uint32_t sb_s = sbase + (uint32_t)(c & 1)*STG;
#pragma unroll
        for (int kk = 0; kk < 32; kk += 16) {
            uint32_t ah[2][4], al[2][4], bh[2][4], bl[2][4];
            const int k16a = (kk >> 3) + (lane >> 4);
            const uint32_t abase = sb_s + aRowOff + ((uint32_t)(k16a ^ srA) << 4);
            ldm4(abase, ah[0]);           ldm4(abase + 16*64, ah[1]);
            ldm4(abase + AL_O, al[0]);    ldm4(abase + AL_O + 16*64, al[1]);
            const int k16b = (kk >> 3) + ((lane >> 3) & 1);
            const uint32_t bbase = sb_s + bRowOff + ((uint32_t)(k16b ^ srB) << 4);
            ldm4(bbase, bh[0]);           ldm4(bbase + 16*64, bh[1]);
            ldm4(bbase + 4096, bl[0]);    ldm4(bbase + 4096 + 16*64, bl[1]);

            // term-outer ordering: RAW distance to same accumulator = 8 MMAs
#pragma unroll
            for (int mt = 0; mt < 2; ++mt)
#pragma unroll
                for (int nt = 0; nt < 4; ++nt)
                    mma16816(acc[mt][nt], ah[mt], &bh[nt >> 1][(nt & 1)*2]);
#pragma unroll
            for (int mt = 0; mt < 2; ++mt)
#pragma unroll
                for (int nt = 0; nt < 4; ++nt)
                    mma16816(acc[mt][nt], ah[mt], &bl[nt >> 1][(nt & 1)*2]);
#pragma unroll
            for (int mt = 0; mt < 2; ++mt)
#pragma unroll
                for (int nt = 0; nt < 4; ++nt)
                    mma16816(acc[mt][nt], al[mt], &bh[nt >> 1][(nt & 1)*2]);
        }
        __syncthreads();
    }

    // epilogue
    const int g = lane >> 2, tg = lane & 3;
#pragma unroll
    for (int mt = 0; mt < 2; ++mt)
#pragma unroll
        for (int nt = 0; nt < 4; ++nt) {
            const int col = bcol + n0w + nt*8 + tg*2;
            const float b0 = bias[col], b1 = bias[col+1];
#pragma unroll
            for (int half = 0; half < 2; ++half) {
                const int row = brow + m0w + mt*16 + g + half*8;
                if (row < Mstore) {
                    float o0 = acc[mt][nt][half*2+0] + b0;
                    float o1 = acc[mt][nt][half*2+1] + b1;
                    const size_t o = (size_t)row*N + col;
                    if (C) { float2 v; v.x = o0; v.y = o1; *(float2*)(C + o) = v; }
                    if (Chi) {
                        unsigned h0,l0,h1,l1;
                        cvt2(o0,h0,l0); cvt2(o1,h1,l1);
                        *(uint32_t*)(Chi + o) = h0 | (h1<<16);
                        *(uint32_t*)(Clo + o) = l0 | (l1<<16);
                    }
                }
            }
        }
}

// ---------------- fused LSTM step ----------------
__global__ __launch_bounds__(256)
void k_step(const float* __restrict__ Gx, const float* __restrict__ W,
            const float* __restrict__ h_in, float* __restrict__ h_out,
            float* __restrict__ c,
            __nv_bfloat16* __restrict__ Hh, __nv_bfloat16* __restrict__ Hl, int t)
{
    __shared__ float Hs[32][36];
    __shared__ float Ws[32][32];
    __shared__ float Gs[32][32];

    const int tid = threadIdx.x;
    const int n0 = blockIdx.x * 8;
    const int col_local = tid & 31;
    const int gate = col_local >> 3;
    const int n_local = col_local & 7;
    const int gcol = gate*HID + n0 + n_local;
    const int bgrp = tid >> 5;

    float acc0 = Gx[(size_t)(t*NB + bgrp*4 + 0)*(4*HID) + gcol];
    float acc1 = Gx[(size_t)(t*NB + bgrp*4 + 1)*(4*HID) + gcol];
    float acc2 = Gx[(size_t)(t*NB + bgrp*4 + 2)*(4*HID) + gcol];
    float acc3 = Gx[(size_t)(t*NB + bgrp*4 + 3)*(4*HID) + gcol];

    const int hr = tid >> 3;
    const int hc = (tid & 7) * 4;
    const int k4 = (tid >> 5) * 4;

    for (int kb = 0; kb < HID; kb += 32) {
        float4 hv = *(const float4*)(h_in + (size_t)hr*HID + kb + hc);
        Hs[hr][hc+0] = hv.x; Hs[hr][hc+1] = hv.y;
        Hs[hr][hc+2] = hv.z; Hs[hr][hc+3] = hv.w;
#pragma unroll
        for (int kk = 0; kk < 4; kk++)
            Ws[k4+kk][col_local] = W[(size_t)(kb + k4 + kk)*(4*HID) + gcol];
        __syncthreads();
#pragma unroll
        for (int k = 0; k < 32; k++) {
            float w = Ws[k][col_local];
            acc0 += Hs[bgrp*4+0][k] * w;
            acc1 += Hs[bgrp*4+1][k] * w;
            acc2 += Hs[bgrp*4+2][k] * w;
            acc3 += Hs[bgrp*4+3][k] * w;
        }
        __syncthreads();
    }

    Gs[bgrp*4+0][col_local] = acc0;
    Gs[bgrp*4+1][col_local] = acc1;
    Gs[bgrp*4+2][col_local] = acc2;
    Gs[bgrp*4+3][col_local] = acc3;
    __syncthreads();

    const int b = tid >> 3;
    const int nn = tid & 7;
    float gi = Gs[b][0*8 + nn];
    float gf = Gs[b][1*8 + nn];
    float go = Gs[b][2*8 + nn];
    float gc = Gs[b][3*8 + nn];
    int n_glob = n0 + nn;
    float cv = c[(size_t)b*HID + n_glob];
    float si = 1.f / (1.f + expf(-gi));
    float sf = 1.f / (1.f + expf(-gf));
    float so = 1.f / (1.f + expf(-go));
    float c_new = sf * cv + si * tanhf(gc);
    float h_new = so * c_new;
    c[(size_t)b*HID + n_glob] = c_new;
    h_out[(size_t)b*HID + n_glob] = h_new;
    unsigned hh, ll;
    cvt2(h_new, hh, ll);
    size_t ho = (size_t)(b*TSTEPS + t)*HID + n_glob;
    ((unsigned short*)Hh)[ho] = (unsigned short)hh;
    ((unsigned short*)Hl)[ho] = (unsigned short)ll;
}

// ---------------- launch ----------------
extern "C" void kernel_launch(void* const* d_in, const int* in_sizes, int n_in,
                              void* d_out, int out_size)
{
    const int*   rnn   = (const int*)  d_in[0];
    const float* sv    = (const float*)d_in[1];
    const float* embed = (const float*)d_in[2];
    const float* U_w   = (const float*)d_in[3];
    const float* U_b   = (const float*)d_in[4];
    const float* S1_w  = (const float*)d_in[5];
    const float* S1_b  = (const float*)d_in[6];
    const float* V_w   = (const float*)d_in[7];
    const float* W_w   = (const float*)d_in[9];
    const float* P_w   = (const float*)d_in[11];
    const float* P_b   = (const float*)d_in[12];
    float* out = (float*)d_out;

    float *Gx,*hb,*c,*b3;
    __nv_bfloat16 *Xh,*Xl,*Uh,*Ul,*Sh,*Sl,*Hh,*Hl,*Bh,*Bl;
    cudaGetSymbolAddress((void**)&Gx, g_Gx);
    cudaGetSymbolAddress((void**)&hb, g_hbuf);
    cudaGetSymbolAddress((void**)&c,  g_c);
    cudaGetSymbolAddress((void**)&b3, g_bias3);
    cudaGetSymbolAddress((void**)&Xh, g_Xh); cudaGetSymbolAddress((void**)&Xl, g_Xl);
    cudaGetSymbolAddress((void**)&Uh, g_Uh); cudaGetSymbolAddress((void**)&Ul, g_Ul);
    cudaGetSymbolAddress((void**)&Sh, g_Sh); cudaGetSymbolAddress((void**)&Sl, g_Sl);
    cudaGetSymbolAddress((void**)&Hh, g_Hh); cudaGetSymbolAddress((void**)&Hl, g_Hl);
    cudaGetSymbolAddress((void**)&Bh, g_Bh); cudaGetSymbolAddress((void**)&Bl, g_Bl);
    float* h0 = hb;
    float* h1 = hb + NB*HID;

    k_gather<<<dim3(TSTEPS, NB), 128>>>(rnn, embed, Xh, Xl);
    k_init<<<(NB*HID + 255)/256, 256>>>(sv, (const float*)d_in[8],
                                        (const float*)d_in[10], h0, c, b3);

    // GEMM1: U = X @ U_w + U_b -> bf16 hi/lo only
    k_convT<<<dim3((4*STY)/32, EMB/32), 256>>>(U_w, Bh, Bl, EMB, 4*STY);
    k_mgemm<<<dim3(MPAD/128, (4*STY)/64), 256>>>(Xh, Xl, Bh, Bl, U_b,
                                                 nullptr, Uh, Ul, 4*STY, EMB, MPAD);
    // GEMM2: S = U @ S1_w + S1_b -> bf16 hi/lo only
    k_convT<<<dim3(STY/32, (4*STY)/32), 256>>>(S1_w, Bh, Bl, 4*STY, STY);
    k_mgemm<<<dim3(MPAD/128, STY/64), 256>>>(Uh, Ul, Bh, Bl, S1_b,
                                             nullptr, Sh, Sl, STY, 4*STY, MPAD);
    // GEMM3: Gx = S @ V_w + (V_b+W_b) -> fp32 only
    k_convT<<<dim3((4*HID)/32, STY/32), 256>>>(V_w, Bh, Bl, STY, 4*HID);
    k_mgemm<<<dim3(MPAD/128, (4*HID)/64), 256>>>(Sh, Sl, Bh, Bl, b3,
                                                 Gx, nullptr, nullptr, 4*HID, STY, MPAD);

    // recurrence: 63 sequential fused steps, h logged as bf16 hi/lo
    for (int t = 0; t < TSTEPS; t++) {
        float* hin  = (t & 1) ? h1 : h0;
        float* hout = (t & 1) ? h0 : h1;
        k_step<<<HID/8, 256>>>(Gx, W_w, hin, hout, c, Hh, Hl, t);
    }

    // GEMM4: out = H @ P_w + P_b -> fp32 d_out
    k_convT<<<dim3(VOCAB/32, HID/32), 256>>>(P_w, Bh, Bl, HID, VOCAB);
    k_mgemm<<<dim3(MPAD/128, VOCAB/64), 256>>>(Hh, Hl, Bh, Bl, P_b,
                                               out, nullptr, nullptr, VOCAB, HID, MROWS);
}